// round 16
// baseline (speedup 1.0000x reference)
#include <cuda_runtime.h>
#include <cuda_bf16.h>
#include <cuda_fp16.h>
#include <math.h>
#include <stdint.h>

#define BB   16
#define SSEQ 1024
#define DD   768
#define HH   12
#define DHH  64
#define DFF_ 3072
#define MTOK (BB*SSEQ)
#define QSCL 0.18033688011112042f   /* 0.125 * log2(e) */

// ---------------- scratch ----------------
__device__ __half  g_x2 [(size_t)MTOK * DD];
__device__ __half  g_h  [(size_t)MTOK * DD];
__device__ __half  g_q  [(size_t)MTOK * DD];
__device__ __half  g_k  [(size_t)MTOK * DD];
__device__ __half  g_v  [(size_t)MTOK * DD];
__device__ __half  g_c  [(size_t)MTOK * DD];
__device__ __half  g_ff [(size_t)MTOK * DFF_];
__device__ __half  g_wq [3 * DD * DD];
__device__ __half  g_wo [DD * DD];
__device__ __half  g_w1 [DD * DFF_];
__device__ __half  g_w2 [DD * DFF_];

// ---------------- helpers ----------------
__device__ __forceinline__ uint32_t smem_u32(const void* p) {
    uint32_t a;
    asm("{ .reg .u64 t; cvta.to.shared.u64 t, %1; cvt.u32.u64 %0, t; }" : "=r"(a) : "l"(p));
    return a;
}
__device__ __forceinline__ float gelu_f(float v) {
    return 0.5f * v * (1.f + erff(v * 0.70710678118654752f));
}

#define CP_ASYNC16(dst, src) \
    asm volatile("cp.async.cg.shared.global [%0], [%1], 16;" :: "r"(dst), "l"(src))
#define CP_COMMIT()  asm volatile("cp.async.commit_group;" ::: "memory")
#define CP_WAIT1()   asm volatile("cp.async.wait_group 1;" ::: "memory")
#define CP_WAIT0()   asm volatile("cp.async.wait_group 0;" ::: "memory")

#define LDSM_X4(r0, r1, r2, r3, a) \
    asm volatile("ldmatrix.sync.aligned.m8n8.x4.shared.b16 {%0,%1,%2,%3}, [%4];" \
        : "=r"(r0), "=r"(r1), "=r"(r2), "=r"(r3) : "r"(a))
#define LDSM_X4T(r0, r1, r2, r3, a) \
    asm volatile("ldmatrix.sync.aligned.m8n8.x4.trans.shared.b16 {%0,%1,%2,%3}, [%4];" \
        : "=r"(r0), "=r"(r1), "=r"(r2), "=r"(r3) : "r"(a))

#define MMAF16(c0, c1, c2, c3, a0, a1, a2, a3, b0, b1) \
    asm volatile("mma.sync.aligned.m16n8k16.row.col.f32.f16.f16.f32 " \
        "{%0,%1,%2,%3}, {%4,%5,%6,%7}, {%8,%9}, {%0,%1,%2,%3};" \
        : "+f"(c0), "+f"(c1), "+f"(c2), "+f"(c3) \
        : "r"(a0), "r"(a1), "r"(a2), "r"(a3), "r"(b0), "r"(b1))

__device__ __forceinline__ void mma_f16(float* c, const uint32_t* a, uint32_t b0, uint32_t b1) {
    MMAF16(c[0], c[1], c[2], c[3], a[0], a[1], a[2], a[3], b0, b1);
}

// ---------------- HMMA GEMM: fp16, 64-wide chunks, 3-stage, A-fragment pipeline ----------------
struct TcP {
    const __half *A, *B;
    const float *bias, *bias1, *bias2, *R;
    const __half *Rh;
    float* Cf; __half* Cs;
    __half *Q, *K_, *V;
    long a_out, a_in, b_out, b_in, c_out, c_in;
    int a_zdiv, b_zdiv, c_zdiv;
    int as_m, bs_n, cs_m;
    int K, N; int act; int qkv;
};

#define RS64  144
#define PL64  (128 * RS64)        // 18432 per plane
#define STG64 (2 * PL64)          // 36864 per stage (A, B)
#define GSMEM (3 * STG64)         // 110592

__global__ void __launch_bounds__(256, 2) tcmm(TcP p)
{
    extern __shared__ __align__(128) char gsm[];

    const int tid = threadIdx.x, wid = tid >> 5, lane = tid & 31;
    const int n0 = blockIdx.x * 128, m0 = blockIdx.y * 128, z = blockIdx.z;
    const int wm = (wid >> 2) * 64;
    const int wn = (wid & 3) * 32;

    const __half* A = p.A + (long)(z / p.a_zdiv) * p.a_out + (long)(z % p.a_zdiv) * p.a_in;
    const __half* B = p.B + (long)(z / p.b_zdiv) * p.b_out + (long)(z % p.b_zdiv) * p.b_in;
    const long coff = (long)(z / p.c_zdiv) * p.c_out + (long)(z % p.c_zdiv) * p.c_in;

    const uint32_t sbase = smem_u32(gsm);
    const int KC = p.K >> 6;

    // precomputed intra-tile LDSM offsets (stage-independent)
    const uint32_t aoff = (uint32_t)(wm + (lane & 15)) * RS64 + (lane >> 4) * 16;
    const uint32_t boff = (uint32_t)(wn + ((lane >> 4) & 1) * 8 + (lane & 7)) * RS64
                        + ((lane >> 3) & 1) * 16;

    float acc[4][4][4];
    #pragma unroll
    for (int i = 0; i < 4; i++)
        #pragma unroll
        for (int j = 0; j < 4; j++)
            #pragma unroll
            for (int r = 0; r < 4; r++) acc[i][j][r] = 0.f;

    auto load_stage = [&](int s, int c) {
        const long kof = (long)c << 6;
        uint32_t dA = sbase + s * STG64;
        uint32_t dB = dA + PL64;
        #pragma unroll
        for (int i = 0; i < 4; i++) {
            int id = tid + i * 256;
            int row = id >> 3, u = id & 7;
            CP_ASYNC16(dA + (uint32_t)(row * RS64 + u * 16),
                       A + (long)(m0 + row) * p.as_m + kof + u * 8);
            CP_ASYNC16(dB + (uint32_t)(row * RS64 + u * 16),
                       B + (long)(n0 + row) * p.bs_n + kof + u * 8);
        }
    };

    load_stage(0, 0); CP_COMMIT();
    load_stage(1, 1); CP_COMMIT();

    for (int c = 0; c < KC; c++) {
        if (c + 1 < KC) { CP_WAIT1(); } else { CP_WAIT0(); }
        __syncthreads();
        if (c + 2 < KC) { load_stage((c + 2) % 3, c + 2); CP_COMMIT(); }

        const uint32_t sA = sbase + (c % 3) * STG64 + aoff;
        const uint32_t sB = sbase + (c % 3) * STG64 + PL64 + boff;

        // A-fragment double-buffer across ks: LDSM(ks+1) issues before MMAs(ks)
        uint32_t af[2][4][4];
        #pragma unroll
        for (int i = 0; i < 4; i++)
            LDSM_X4(af[0][i][0], af[0][i][1], af[0][i][2], af[0][i][3],
                    sA + (uint32_t)(i * 16) * RS64);

        #pragma unroll
        for (int ks = 0; ks < 4; ks++) {
            const int cur = ks & 1;
            if (ks < 3) {
                #pragma unroll
                for (int i = 0; i < 4; i++)
                    LDSM_X4(af[cur ^ 1][i][0], af[cur ^ 1][i][1],
                            af[cur ^ 1][i][2], af[cur ^ 1][i][3],
                            sA + (uint32_t)(i * 16) * RS64 + (ks + 1) * 32);
            }
            uint32_t b[4][2];
            #pragma unroll
            for (int j = 0; j < 2; j++)
                LDSM_X4(b[2*j][0], b[2*j][1], b[2*j+1][0], b[2*j+1][1],
                        sB + (uint32_t)(j * 16) * RS64 + ks * 32);
            #pragma unroll
            for (int i = 0; i < 4; i++)
                #pragma unroll
                for (int j = 0; j < 4; j++)
                    MMAF16(acc[i][j][0], acc[i][j][1], acc[i][j][2], acc[i][j][3],
                           af[cur][i][0], af[cur][i][1], af[cur][i][2], af[cur][i][3],
                           b[j][0], b[j][1]);
        }
    }

    // epilogue (no bounds checks; N % 128 == 0)
    #pragma unroll
    for (int i = 0; i < 4; i++) {
        #pragma unroll
        for (int j = 0; j < 4; j++) {
            int n = n0 + wn + j * 8 + (lane & 3) * 2;
            #pragma unroll
            for (int half_ = 0; half_ < 2; half_++) {
                int m = m0 + wm + i * 16 + (lane >> 2) + half_ * 8;
                float vx = acc[i][j][half_ * 2 + 0];
                float vy = acc[i][j][half_ * 2 + 1];
                const long base = coff + (long)m * p.cs_m + n;
                if (p.qkv) {
                    const float* bias = (z == 0) ? p.bias : (z == 1) ? p.bias1 : p.bias2;
                    vx += bias[n]; vy += bias[n + 1];
                    float sc = (z == 0) ? QSCL : 1.f;
                    __half* o = (z == 0) ? p.Q : (z == 1) ? p.K_ : p.V;
                    *(__half2*)(o + base) = __floats2half2_rn(vx * sc, vy * sc);
                } else {
                    if (p.bias) { vx += p.bias[n]; vy += p.bias[n + 1]; }
                    if (p.act)  { vx = gelu_f(vx); vy = gelu_f(vy); }
                    if (p.R) {
                        float2 rr = *(const float2*)(p.R + base);
                        vx += rr.x; vy += rr.y;
                    }
                    if (p.Rh) {
                        float2 rr = __half22float2(*(const __half2*)(p.Rh + base));
                        vx += rr.x; vy += rr.y;
                    }
                    if (p.Cf) *(float2*)(p.Cf + base) = make_float2(vx, vy);
                    if (p.Cs) *(__half2*)(p.Cs + base) = __floats2half2_rn(vx, vy);
                }
            }
        }
    }
}

// ---------------- Flash attention: static softmax, tensor-core row sums ----------------
#define FRS   144
#define FQPL  (128 * FRS)
#define FKPL  (64 * FRS)
#define FSTG  (2 * FKPL)
#define FSMEM (FQPL + 3 * FSTG)   // 73728
#define NKT   16

__global__ void __launch_bounds__(256, 2) flash_attn(
    const __half* __restrict__ q,
    const __half* __restrict__ k,
    const __half* __restrict__ v,
    __half* __restrict__ ch)
{
    extern __shared__ __align__(128) char fsm[];
    const int tid = threadIdx.x, wid = tid >> 5, lane = tid & 31;
    const int b = blockIdx.z / HH, h = blockIdx.z % HH;
    const size_t qrow0 = (size_t)b * SSEQ + blockIdx.x * 128;
    const size_t krow0 = (size_t)b * SSEQ;
    const int hc = h * DHH;

    const uint32_t sb  = smem_u32(fsm);
    const uint32_t sKV = sb + FQPL;

    {
        #pragma unroll
        for (int i = 0; i < 4; i++) {
            int id = tid + i * 256;
            int row = id >> 3, cu = id & 7;
            CP_ASYNC16(sb + (uint32_t)(row * FRS + cu * 16),
                       q + (qrow0 + row) * DD + hc + cu * 8);
        }
    }
    auto loadKV = [&](int kt, int s) {
        uint32_t base = sKV + (uint32_t)s * FSTG;
        size_t r0 = krow0 + (size_t)kt * 64;
        #pragma unroll
        for (int i = 0; i < 4; i++) {
            int id = tid + i * 256;
            int pl = id >> 9, rc = id & 511;
            int row = rc >> 3, cu = rc & 7;
            const __half* g = pl ? v : k;
            CP_ASYNC16(base + (uint32_t)(pl * FKPL + row * FRS + cu * 16),
                       g + (r0 + row) * DD + hc + cu * 8);
        }
    };
    loadKV(0, 0); CP_COMMIT();
    loadKV(1, 1); CP_COMMIT();
    CP_WAIT1(); __syncthreads();

    uint32_t qf[4][4];
    const int mw = wid * 16;
    #pragma unroll
    for (int kf = 0; kf < 4; kf++) {
        uint32_t ad = sb + (uint32_t)((mw + (lane & 15)) * FRS + kf * 32 + (lane >> 4) * 16);
        LDSM_X4(qf[kf][0], qf[kf][1], qf[kf][2], qf[kf][3], ad);
    }

    float accO[8][4];
    #pragma unroll
    for (int i = 0; i < 8; i++) { accO[i][0] = accO[i][1] = accO[i][2] = accO[i][3] = 0.f; }
    float lacc[4] = {0.f, 0.f, 0.f, 0.f};
    const uint32_t ONES2 = 0x3C003C00u;

    for (int kt = 0; kt < NKT; kt++) {
        if (kt + 1 < NKT) { CP_WAIT1(); } else { CP_WAIT0(); }
        __syncthreads();
        if (kt + 2 < NKT) { loadKV(kt + 2, (kt + 2) % 3); CP_COMMIT(); }

        const uint32_t bK = sKV + (uint32_t)(kt % 3) * FSTG;
        const uint32_t bV = bK + FKPL;

        float S[8][4];
        #pragma unroll
        for (int j = 0; j < 8; j++) { S[j][0] = S[j][1] = S[j][2] = S[j][3] = 0.f; }

        #pragma unroll
        for (int kf = 0; kf < 4; kf++) {
            #pragma unroll
            for (int jp = 0; jp < 4; jp++) {
                uint32_t b0, b1, b2, b3;
                uint32_t ad = bK + (uint32_t)((jp * 16 + ((lane >> 4) & 1) * 8 + (lane & 7)) * FRS
                            + kf * 32 + ((lane >> 3) & 1) * 16);
                LDSM_X4(b0, b1, b2, b3, ad);
                mma_f16(S[2 * jp],     qf[kf], b0, b1);
                mma_f16(S[2 * jp + 1], qf[kf], b2, b3);
            }
        }

        #pragma unroll
        for (int kf = 0; kf < 4; kf++) {
            __half2 e0 = h2exp2(__floats2half2_rn(S[2*kf][0],   S[2*kf][1]));
            __half2 e1 = h2exp2(__floats2half2_rn(S[2*kf][2],   S[2*kf][3]));
            __half2 e2 = h2exp2(__floats2half2_rn(S[2*kf+1][0], S[2*kf+1][1]));
            __half2 e3 = h2exp2(__floats2half2_rn(S[2*kf+1][2], S[2*kf+1][3]));
            uint32_t pa[4];
            pa[0] = *reinterpret_cast<uint32_t*>(&e0);
            pa[1] = *reinterpret_cast<uint32_t*>(&e1);
            pa[2] = *reinterpret_cast<uint32_t*>(&e2);
            pa[3] = *reinterpret_cast<uint32_t*>(&e3);

            mma_f16(lacc, pa, ONES2, ONES2);

            #pragma unroll
            for (int np = 0; np < 4; np++) {
                uint32_t ad = bV + (uint32_t)((kf * 16 + ((lane >> 3) & 1) * 8 + (lane & 7)) * FRS
                            + np * 32 + (lane >> 4) * 16);
                uint32_t v0, v1, v2, v3;
                LDSM_X4T(v0, v1, v2, v3, ad);
                mma_f16(accO[2 * np],     pa, v0, v1);
                mma_f16(accO[2 * np + 1], pa, v2, v3);
            }
        }
    }

    float inv0 = 1.f / lacc[0], inv1 = 1.f / lacc[2];
    size_t r0 = qrow0 + mw + (lane >> 2);
    #pragma unroll
    for (int nt = 0; nt < 8; nt++) {
        int col = hc + nt * 8 + 2 * (lane & 3);
        *(__half2*)(ch + r0 * DD + col) =
            __floats2half2_rn(accO[nt][0] * inv0, accO[nt][1] * inv0);
        *(__half2*)(ch + (r0 + 8) * DD + col) =
            __floats2half2_rn(accO[nt][2] * inv1, accO[nt][3] * inv1);
    }
}

// ---------------- fused weight prep + ln1 (independent work, one launch) ----------------
#define QKVN (DD * DD)
#define WON  (DD * DD)
#define W12N (DD * DFF_)
#define PREP_TOT ((long)QKVN + WON + 2L * W12N)
#define PREP_NB  ((unsigned)((PREP_TOT + 255) / 256))

__global__ void __launch_bounds__(256) prep_ln1(
    const float* __restrict__ Wq, const float* __restrict__ Wk, const float* __restrict__ Wv,
    const float* __restrict__ Wo, const float* __restrict__ W1, const float* __restrict__ W2,
    __half* __restrict__ wq, __half* __restrict__ wo,
    __half* __restrict__ w1, __half* __restrict__ w2,
    const float* __restrict__ x, const float* __restrict__ g, const float* __restrict__ b,
    __half* __restrict__ oh)
{
    if (blockIdx.x >= PREP_NB) {
        // ---- ln1 row ----
        size_t row = blockIdx.x - PREP_NB;
        const float* xr = x + row * DD;
        int t = threadIdx.x;
        float v0 = xr[t], v1 = xr[t + 256], v2 = xr[t + 512];
        float s  = v0 + v1 + v2;
        float s2 = v0*v0 + v1*v1 + v2*v2;
        #pragma unroll
        for (int o = 16; o; o >>= 1) {
            s  += __shfl_xor_sync(0xFFFFFFFFu, s,  o);
            s2 += __shfl_xor_sync(0xFFFFFFFFu, s2, o);
        }
        __shared__ float sh[2][8];
        int w = t >> 5, l = t & 31;
        if (l == 0) { sh[0][w] = s; sh[1][w] = s2; }
        __syncthreads();
        s = 0.f; s2 = 0.f;
        #pragma unroll
        for (int i = 0; i < 8; i++) { s += sh[0][i]; s2 += sh[1][i]; }
        float mean = s * (1.f / 768.f);
        float var  = s2 * (1.f / 768.f) - mean * mean;
        float inv  = rsqrtf(var + 1e-5f);
        oh[row*DD + t]       = __float2half_rn((v0 - mean) * inv * g[t]       + b[t]);
        oh[row*DD + t + 256] = __float2half_rn((v1 - mean) * inv * g[t + 256] + b[t + 256]);
        oh[row*DD + t + 512] = __float2half_rn((v2 - mean) * inv * g[t + 512] + b[t + 512]);
        return;
    }
    // ---- weight prep ----
    long idx = (long)blockIdx.x * 256 + threadIdx.x;
    if (idx < QKVN) {
        int n = (int)(idx / DD), d = (int)(idx % DD);
        int h = n >> 6, cc = n & 63;
        size_t src = (size_t)h * DD * DHH + (size_t)d * DHH + cc;
        wq[idx]            = __float2half_rn(Wq[src]);
        wq[idx + QKVN]     = __float2half_rn(Wk[src]);
        wq[idx + 2 * QKVN] = __float2half_rn(Wv[src]);
        return;
    }
    idx -= QKVN;
    if (idx < WON) {
        int n = (int)(idx / DD), kk = (int)(idx % DD);
        wo[idx] = __float2half_rn(Wo[(long)kk * DD + n]);
        return;
    }
    idx -= WON;
    if (idx < W12N) {
        int n = (int)(idx / DD), kk = (int)(idx % DD);
        w1[idx] = __float2half_rn(W1[(long)kk * DFF_ + n]);
        return;
    }
    idx -= W12N;
    if (idx < W12N) {
        int n = (int)(idx / DFF_), kk = (int)(idx % DFF_);
        w2[idx] = __float2half_rn(W2[(long)kk * DD + n]);
    }
}

// ---------------- LayerNorm (fp16 in) -> fp16 ----------------
__global__ void __launch_bounds__(256) lnorm_h_kernel(
    const __half* __restrict__ x, const float* __restrict__ g, const float* __restrict__ b,
    __half* __restrict__ oh)
{
    size_t row = blockIdx.x;
    const __half* xr = x + row * DD;
    int t = threadIdx.x;
    float v0 = __half2float(xr[t]);
    float v1 = __half2float(xr[t + 256]);
    float v2 = __half2float(xr[t + 512]);
    float s  = v0 + v1 + v2;
    float s2 = v0*v0 + v1*v1 + v2*v2;
    #pragma unroll
    for (int o = 16; o; o >>= 1) {
        s  += __shfl_xor_sync(0xFFFFFFFFu, s,  o);
        s2 += __shfl_xor_sync(0xFFFFFFFFu, s2, o);
    }
    __shared__ float sh[2][8];
    int w = t >> 5, l = t & 31;
    if (l == 0) { sh[0][w] = s; sh[1][w] = s2; }
    __syncthreads();
    s = 0.f; s2 = 0.f;
    #pragma unroll
    for (int i = 0; i < 8; i++) { s += sh[0][i]; s2 += sh[1][i]; }
    float mean = s * (1.f / 768.f);
    float var  = s2 * (1.f / 768.f) - mean * mean;
    float inv  = rsqrtf(var + 1e-5f);
    oh[row*DD + t]       = __float2half_rn((v0 - mean) * inv * g[t]       + b[t]);
    oh[row*DD + t + 256] = __float2half_rn((v1 - mean) * inv * g[t + 256] + b[t + 256]);
    oh[row*DD + t + 512] = __float2half_rn((v2 - mean) * inv * g[t + 512] + b[t + 512]);
}

// ---------------- host ----------------
extern "C" void kernel_launch(void* const* d_in, const int* in_sizes, int n_in,
                              void* d_out, int out_size)
{
    (void)in_sizes; (void)n_in; (void)out_size;
    const float* x    = (const float*)d_in[0];
    const float* ln1g = (const float*)d_in[1];
    const float* ln1b = (const float*)d_in[2];
    const float* Wq   = (const float*)d_in[3];
    const float* bq   = (const float*)d_in[4];
    const float* Wk   = (const float*)d_in[5];
    const float* bk   = (const float*)d_in[6];
    const float* Wv   = (const float*)d_in[7];
    const float* bv   = (const float*)d_in[8];
    const float* Wo   = (const float*)d_in[9];
    const float* bo   = (const float*)d_in[10];
    const float* ln2g = (const float*)d_in[11];
    const float* ln2b = (const float*)d_in[12];
    const float* W1   = (const float*)d_in[13];
    const float* b1   = (const float*)d_in[14];
    const float* W2   = (const float*)d_in[15];
    const float* b2   = (const float*)d_in[16];
    float* out = (float*)d_out;

    __half *x2, *h, *q, *k, *v, *c, *ff, *wq, *wo, *w1, *w2;
    cudaGetSymbolAddress((void**)&x2,  g_x2);
    cudaGetSymbolAddress((void**)&h,   g_h);
    cudaGetSymbolAddress((void**)&q,   g_q);
    cudaGetSymbolAddress((void**)&k,   g_k);
    cudaGetSymbolAddress((void**)&v,   g_v);
    cudaGetSymbolAddress((void**)&c,   g_c);
    cudaGetSymbolAddress((void**)&ff,  g_ff);
    cudaGetSymbolAddress((void**)&wq,  g_wq);
    cudaGetSymbolAddress((void**)&wo,  g_wo);
    cudaGetSymbolAddress((void**)&w1,  g_w1);
    cudaGetSymbolAddress((void**)&w2,  g_w2);

    cudaFuncSetAttribute(tcmm, cudaFuncAttributeMaxDynamicSharedMemorySize, GSMEM);
    cudaFuncSetAttribute(flash_attn, cudaFuncAttributeMaxDynamicSharedMemorySize, FSMEM);

    // fused weight prep + ln1
    prep_ln1<<<PREP_NB + MTOK, 256>>>(
        Wq, Wk, Wv, Wo, W1, W2, wq, wo, w1, w2, x, ln1g, ln1b, h);

    // fused QKV projection (z = 0:q, 1:k, 2:v)
    {
        TcP p{};
        p.A = h; p.as_m = DD; p.a_out = 0; p.a_in = 0; p.a_zdiv = 1;
        p.B = wq; p.bs_n = DD;
        p.b_out = (long)DD * DD; p.b_in = 0; p.b_zdiv = 1;
        p.cs_m = DD; p.c_out = 0; p.c_in = 0; p.c_zdiv = 1;
        p.K = DD; p.N = DD; p.act = 0; p.qkv = 1;
        p.bias = bq; p.bias1 = bk; p.bias2 = bv;
        p.Q = q; p.K_ = k; p.V = v;
        tcmm<<<dim3(DD / 128, MTOK / 128, 3), 256, GSMEM>>>(p);
    }

    flash_attn<<<dim3(SSEQ / 128, 1, BB * HH), 256, FSMEM>>>(q, k, v, c);

    // x2 = fp16( x + ctx @ Wo + bo )
    {
        TcP s{};
        s.A = c; s.as_m = DD; s.a_out = 0; s.a_in = 0; s.a_zdiv = 1;
        s.B = wo; s.bs_n = DD; s.b_out = 0; s.b_in = 0; s.b_zdiv = 1;
        s.bias = bo; s.R = x;
        s.Cs = x2;
        s.cs_m = DD; s.c_out = 0; s.c_in = 0; s.c_zdiv = 1;
        s.K = DD; s.N = DD; s.act = 0; s.qkv = 0;
        tcmm<<<dim3(DD / 128, MTOK / 128, 1), 256, GSMEM>>>(s);
    }

    lnorm_h_kernel<<<MTOK, 256>>>(x2, ln2g, ln2b, h);

    // ff = gelu(h @ W1 + b1)
    {
        TcP s{};
        s.A = h; s.as_m = DD; s.a_out = 0; s.a_in = 0; s.a_zdiv = 1;
        s.B = w1; s.bs_n = DD; s.b_out = 0; s.b_in = 0; s.b_zdiv = 1;
        s.bias = b1;
        s.Cs = ff;
        s.cs_m = DFF_; s.c_out = 0; s.c_in = 0; s.c_zdiv = 1;
        s.K = DD; s.N = DFF_; s.act = 1; s.qkv = 0;
        tcmm<<<dim3(DFF_ / 128, MTOK / 128, 1), 256, GSMEM>>>(s);
    }

    // out = x2 + ff @ W2 + b2   (fp32 output)
    {
        TcP s{};
        s.A = ff; s.as_m = DFF_; s.a_out = 0; s.a_in = 0; s.a_zdiv = 1;
        s.B = w2; s.bs_n = DFF_; s.b_out = 0; s.b_in = 0; s.b_zdiv = 1;
        s.bias = b2; s.Rh = x2;
        s.Cf = out;
        s.cs_m = DD; s.c_out = 0; s.c_in = 0; s.c_zdiv = 1;
        s.K = DFF_; s.N = DD; s.act = 0; s.qkv = 0;
        tcmm<<<dim3(DD / 128, MTOK / 128, 1), 256, GSMEM>>>(s);
    }
}

// round 17
// speedup vs baseline: 1.0229x; 1.0229x over previous
#include <cuda_runtime.h>
#include <cuda_bf16.h>
#include <cuda_fp16.h>
#include <math.h>
#include <stdint.h>

#define BB   16
#define SSEQ 1024
#define DD   768
#define HH   12
#define DHH  64
#define DFF_ 3072
#define MTOK (BB*SSEQ)
#define QSCL 0.18033688011112042f   /* 0.125 * log2(e) */

// ---------------- scratch ----------------
__device__ __half  g_x2 [(size_t)MTOK * DD];
__device__ __half  g_h  [(size_t)MTOK * DD];
__device__ __half  g_q  [(size_t)MTOK * DD];
__device__ __half  g_k  [(size_t)MTOK * DD];
__device__ __half  g_v  [(size_t)MTOK * DD];
__device__ __half  g_c  [(size_t)MTOK * DD];
__device__ __half  g_ff [(size_t)MTOK * DFF_];
__device__ __half  g_wq [3 * DD * DD];
__device__ __half  g_wo [DD * DD];
__device__ __half  g_w1 [DD * DFF_];
__device__ __half  g_w2 [DD * DFF_];

// ---------------- helpers ----------------
__device__ __forceinline__ uint32_t smem_u32(const void* p) {
    uint32_t a;
    asm("{ .reg .u64 t; cvta.to.shared.u64 t, %1; cvt.u32.u64 %0, t; }" : "=r"(a) : "l"(p));
    return a;
}
__device__ __forceinline__ float gelu_f(float v) {
    return 0.5f * v * (1.f + erff(v * 0.70710678118654752f));
}

#define CP_ASYNC16(dst, src) \
    asm volatile("cp.async.cg.shared.global [%0], [%1], 16;" :: "r"(dst), "l"(src))
#define CP_COMMIT()  asm volatile("cp.async.commit_group;" ::: "memory")
#define CP_WAIT1()   asm volatile("cp.async.wait_group 1;" ::: "memory")
#define CP_WAIT0()   asm volatile("cp.async.wait_group 0;" ::: "memory")

#define LDSM_X4(r0, r1, r2, r3, a) \
    asm volatile("ldmatrix.sync.aligned.m8n8.x4.shared.b16 {%0,%1,%2,%3}, [%4];" \
        : "=r"(r0), "=r"(r1), "=r"(r2), "=r"(r3) : "r"(a))
#define LDSM_X4T(r0, r1, r2, r3, a) \
    asm volatile("ldmatrix.sync.aligned.m8n8.x4.trans.shared.b16 {%0,%1,%2,%3}, [%4];" \
        : "=r"(r0), "=r"(r1), "=r"(r2), "=r"(r3) : "r"(a))

#define MMAF16(c0, c1, c2, c3, a0, a1, a2, a3, b0, b1) \
    asm volatile("mma.sync.aligned.m16n8k16.row.col.f32.f16.f16.f32 " \
        "{%0,%1,%2,%3}, {%4,%5,%6,%7}, {%8,%9}, {%0,%1,%2,%3};" \
        : "+f"(c0), "+f"(c1), "+f"(c2), "+f"(c3) \
        : "r"(a0), "r"(a1), "r"(a2), "r"(a3), "r"(b0), "r"(b1))

__device__ __forceinline__ void mma_f16(float* c, const uint32_t* a, uint32_t b0, uint32_t b1) {
    MMAF16(c[0], c[1], c[2], c[3], a[0], a[1], a[2], a[3], b0, b1);
}

// ---------------- HMMA GEMM: fp16, 64-wide k-chunks, 3-stage, 64x32 warp tiles ----------------
struct TcP {
    const __half *A, *B;
    const float *bias, *bias1, *bias2, *R;
    const __half *Rh;
    float* Cf; __half* Cs;
    __half *Q, *K_, *V;
    long a_out, a_in, b_out, b_in, c_out, c_in;
    int a_zdiv, b_zdiv, c_zdiv;
    int as_m, bs_n, cs_m;
    int K, N; int act; int qkv;
};

#define RS64  144
#define PL64  (128 * RS64)        // 18432 per plane
#define STG64 (2 * PL64)          // 36864 per stage (A, B)
#define GSMEM (3 * STG64)         // 110592

__global__ void __launch_bounds__(256, 2) tcmm(TcP p)
{
    extern __shared__ __align__(128) char gsm[];

    const int tid = threadIdx.x, wid = tid >> 5, lane = tid & 31;
    const int n0 = blockIdx.x * 128, m0 = blockIdx.y * 128, z = blockIdx.z;
    const int wm = (wid >> 2) * 64;
    const int wn = (wid & 3) * 32;

    const __half* A = p.A + (long)(z / p.a_zdiv) * p.a_out + (long)(z % p.a_zdiv) * p.a_in;
    const __half* B = p.B + (long)(z / p.b_zdiv) * p.b_out + (long)(z % p.b_zdiv) * p.b_in;
    const long coff = (long)(z / p.c_zdiv) * p.c_out + (long)(z % p.c_zdiv) * p.c_in;

    const uint32_t sbase = smem_u32(gsm);
    const int KC = p.K >> 6;          // 64-wide chunks

    float acc[4][4][4];
    #pragma unroll
    for (int i = 0; i < 4; i++)
        #pragma unroll
        for (int j = 0; j < 4; j++)
            #pragma unroll
            for (int r = 0; r < 4; r++) acc[i][j][r] = 0.f;

    auto load_stage = [&](int s, int c) {
        const long kof = (long)c << 6;
        uint32_t dA = sbase + s * STG64;
        uint32_t dB = dA + PL64;
        #pragma unroll
        for (int i = 0; i < 4; i++) {
            int id = tid + i * 256;
            int row = id >> 3, u = id & 7;
            CP_ASYNC16(dA + (uint32_t)(row * RS64 + u * 16),
                       A + (long)(m0 + row) * p.as_m + kof + u * 8);
            CP_ASYNC16(dB + (uint32_t)(row * RS64 + u * 16),
                       B + (long)(n0 + row) * p.bs_n + kof + u * 8);
        }
    };

    load_stage(0, 0); CP_COMMIT();
    load_stage(1, 1); CP_COMMIT();

    for (int c = 0; c < KC; c++) {
        if (c + 1 < KC) { CP_WAIT1(); } else { CP_WAIT0(); }
        __syncthreads();
        if (c + 2 < KC) { load_stage((c + 2) % 3, c + 2); CP_COMMIT(); }

        const uint32_t sA = sbase + (c % 3) * STG64;
        const uint32_t sB = sA + PL64;

        #pragma unroll
        for (int ks = 0; ks < 4; ks++) {
            uint32_t a[4][4], b[4][2];
            #pragma unroll
            for (int i = 0; i < 4; i++) {
                uint32_t ad = sA + (uint32_t)(wm + i * 16 + (lane & 15)) * RS64
                            + ks * 32 + (lane >> 4) * 16;
                LDSM_X4(a[i][0], a[i][1], a[i][2], a[i][3], ad);
            }
            #pragma unroll
            for (int j = 0; j < 2; j++) {
                uint32_t bd = sB + (uint32_t)(wn + j * 16 + ((lane >> 4) & 1) * 8 + (lane & 7)) * RS64
                            + ks * 32 + ((lane >> 3) & 1) * 16;
                LDSM_X4(b[2*j][0], b[2*j][1], b[2*j+1][0], b[2*j+1][1], bd);
            }
            #pragma unroll
            for (int i = 0; i < 4; i++)
                #pragma unroll
                for (int j = 0; j < 4; j++)
                    MMAF16(acc[i][j][0], acc[i][j][1], acc[i][j][2], acc[i][j][3],
                           a[i][0], a[i][1], a[i][2], a[i][3], b[j][0], b[j][1]);
        }
    }

    // epilogue (no bounds checks; N % 128 == 0)
    #pragma unroll
    for (int i = 0; i < 4; i++) {
        #pragma unroll
        for (int j = 0; j < 4; j++) {
            int n = n0 + wn + j * 8 + (lane & 3) * 2;
            #pragma unroll
            for (int half_ = 0; half_ < 2; half_++) {
                int m = m0 + wm + i * 16 + (lane >> 2) + half_ * 8;
                float vx = acc[i][j][half_ * 2 + 0];
                float vy = acc[i][j][half_ * 2 + 1];
                const long base = coff + (long)m * p.cs_m + n;
                if (p.qkv) {
                    const float* bias = (z == 0) ? p.bias : (z == 1) ? p.bias1 : p.bias2;
                    vx += bias[n]; vy += bias[n + 1];
                    float sc = (z == 0) ? QSCL : 1.f;
                    __half* o = (z == 0) ? p.Q : (z == 1) ? p.K_ : p.V;
                    *(__half2*)(o + base) = __floats2half2_rn(vx * sc, vy * sc);
                } else {
                    if (p.bias) { vx += p.bias[n]; vy += p.bias[n + 1]; }
                    if (p.act)  { vx = gelu_f(vx); vy = gelu_f(vy); }
                    if (p.R) {
                        float2 rr = *(const float2*)(p.R + base);
                        vx += rr.x; vy += rr.y;
                    }
                    if (p.Rh) {
                        float2 rr = __half22float2(*(const __half2*)(p.Rh + base));
                        vx += rr.x; vy += rr.y;
                    }
                    if (p.Cf) *(float2*)(p.Cf + base) = make_float2(vx, vy);
                    if (p.Cs) *(__half2*)(p.Cs + base) = __floats2half2_rn(vx, vy);
                }
            }
        }
    }
}

// ---------------- Flash attention: static softmax, tensor-core row sums ----------------
#define FRS   144
#define FQPL  (128 * FRS)
#define FKPL  (64 * FRS)
#define FSTG  (2 * FKPL)
#define FSMEM (FQPL + 3 * FSTG)   // 73728
#define NKT   16

__global__ void __launch_bounds__(256, 2) flash_attn(
    const __half* __restrict__ q,
    const __half* __restrict__ k,
    const __half* __restrict__ v,
    __half* __restrict__ ch)
{
    extern __shared__ __align__(128) char fsm[];
    const int tid = threadIdx.x, wid = tid >> 5, lane = tid & 31;
    const int b = blockIdx.z / HH, h = blockIdx.z % HH;
    const size_t qrow0 = (size_t)b * SSEQ + blockIdx.x * 128;
    const size_t krow0 = (size_t)b * SSEQ;
    const int hc = h * DHH;

    const uint32_t sb  = smem_u32(fsm);
    const uint32_t sKV = sb + FQPL;

    {
        #pragma unroll
        for (int i = 0; i < 4; i++) {
            int id = tid + i * 256;
            int row = id >> 3, cu = id & 7;
            CP_ASYNC16(sb + (uint32_t)(row * FRS + cu * 16),
                       q + (qrow0 + row) * DD + hc + cu * 8);
        }
    }
    auto loadKV = [&](int kt, int s) {
        uint32_t base = sKV + (uint32_t)s * FSTG;
        size_t r0 = krow0 + (size_t)kt * 64;
        #pragma unroll
        for (int i = 0; i < 4; i++) {
            int id = tid + i * 256;
            int pl = id >> 9, rc = id & 511;
            int row = rc >> 3, cu = rc & 7;
            const __half* g = pl ? v : k;
            CP_ASYNC16(base + (uint32_t)(pl * FKPL + row * FRS + cu * 16),
                       g + (r0 + row) * DD + hc + cu * 8);
        }
    };
    loadKV(0, 0); CP_COMMIT();
    loadKV(1, 1); CP_COMMIT();
    CP_WAIT1(); __syncthreads();

    uint32_t qf[4][4];
    const int mw = wid * 16;
    #pragma unroll
    for (int kf = 0; kf < 4; kf++) {
        uint32_t ad = sb + (uint32_t)((mw + (lane & 15)) * FRS + kf * 32 + (lane >> 4) * 16);
        LDSM_X4(qf[kf][0], qf[kf][1], qf[kf][2], qf[kf][3], ad);
    }

    float accO[8][4];
    #pragma unroll
    for (int i = 0; i < 8; i++) { accO[i][0] = accO[i][1] = accO[i][2] = accO[i][3] = 0.f; }
    float lacc[4] = {0.f, 0.f, 0.f, 0.f};
    const uint32_t ONES2 = 0x3C003C00u;

    for (int kt = 0; kt < NKT; kt++) {
        if (kt + 1 < NKT) { CP_WAIT1(); } else { CP_WAIT0(); }
        __syncthreads();
        if (kt + 2 < NKT) { loadKV(kt + 2, (kt + 2) % 3); CP_COMMIT(); }

        const uint32_t bK = sKV + (uint32_t)(kt % 3) * FSTG;
        const uint32_t bV = bK + FKPL;

        float S[8][4];
        #pragma unroll
        for (int j = 0; j < 8; j++) { S[j][0] = S[j][1] = S[j][2] = S[j][3] = 0.f; }

        #pragma unroll
        for (int kf = 0; kf < 4; kf++) {
            #pragma unroll
            for (int jp = 0; jp < 4; jp++) {
                uint32_t b0, b1, b2, b3;
                uint32_t ad = bK + (uint32_t)((jp * 16 + ((lane >> 4) & 1) * 8 + (lane & 7)) * FRS
                            + kf * 32 + ((lane >> 3) & 1) * 16);
                LDSM_X4(b0, b1, b2, b3, ad);
                mma_f16(S[2 * jp],     qf[kf], b0, b1);
                mma_f16(S[2 * jp + 1], qf[kf], b2, b3);
            }
        }

        #pragma unroll
        for (int kf = 0; kf < 4; kf++) {
            __half2 e0 = h2exp2(__floats2half2_rn(S[2*kf][0],   S[2*kf][1]));
            __half2 e1 = h2exp2(__floats2half2_rn(S[2*kf][2],   S[2*kf][3]));
            __half2 e2 = h2exp2(__floats2half2_rn(S[2*kf+1][0], S[2*kf+1][1]));
            __half2 e3 = h2exp2(__floats2half2_rn(S[2*kf+1][2], S[2*kf+1][3]));
            uint32_t pa[4];
            pa[0] = *reinterpret_cast<uint32_t*>(&e0);
            pa[1] = *reinterpret_cast<uint32_t*>(&e1);
            pa[2] = *reinterpret_cast<uint32_t*>(&e2);
            pa[3] = *reinterpret_cast<uint32_t*>(&e3);

            mma_f16(lacc, pa, ONES2, ONES2);

            #pragma unroll
            for (int np = 0; np < 4; np++) {
                uint32_t ad = bV + (uint32_t)((kf * 16 + ((lane >> 3) & 1) * 8 + (lane & 7)) * FRS
                            + np * 32 + (lane >> 4) * 16);
                uint32_t v0, v1, v2, v3;
                LDSM_X4T(v0, v1, v2, v3, ad);
                mma_f16(accO[2 * np],     pa, v0, v1);
                mma_f16(accO[2 * np + 1], pa, v2, v3);
            }
        }
    }

    float inv0 = 1.f / lacc[0], inv1 = 1.f / lacc[2];
    size_t r0 = qrow0 + mw + (lane >> 2);
    #pragma unroll
    for (int nt = 0; nt < 8; nt++) {
        int col = hc + nt * 8 + 2 * (lane & 3);
        *(__half2*)(ch + r0 * DD + col) =
            __floats2half2_rn(accO[nt][0] * inv0, accO[nt][1] * inv0);
        *(__half2*)(ch + (r0 + 8) * DD + col) =
            __floats2half2_rn(accO[nt][2] * inv1, accO[nt][3] * inv1);
    }
}

// ---------------- fused weight prep + ln1 ----------------
#define QKVN (DD * DD)
#define WON  (DD * DD)
#define W12N (DD * DFF_)
#define PREP_TOT ((long)QKVN + WON + 2L * W12N)
#define PREP_NB  ((unsigned)((PREP_TOT + 255) / 256))

__global__ void __launch_bounds__(256) prep_ln1(
    const float* __restrict__ Wq, const float* __restrict__ Wk, const float* __restrict__ Wv,
    const float* __restrict__ Wo, const float* __restrict__ W1, const float* __restrict__ W2,
    __half* __restrict__ wq, __half* __restrict__ wo,
    __half* __restrict__ w1, __half* __restrict__ w2,
    const float* __restrict__ x, const float* __restrict__ g, const float* __restrict__ b,
    __half* __restrict__ oh)
{
    if (blockIdx.x >= PREP_NB) {
        size_t row = blockIdx.x - PREP_NB;
        const float* xr = x + row * DD;
        int t = threadIdx.x;
        float v0 = xr[t], v1 = xr[t + 256], v2 = xr[t + 512];
        float s  = v0 + v1 + v2;
        float s2 = v0*v0 + v1*v1 + v2*v2;
        #pragma unroll
        for (int o = 16; o; o >>= 1) {
            s  += __shfl_xor_sync(0xFFFFFFFFu, s,  o);
            s2 += __shfl_xor_sync(0xFFFFFFFFu, s2, o);
        }
        __shared__ float sh[2][8];
        int w = t >> 5, l = t & 31;
        if (l == 0) { sh[0][w] = s; sh[1][w] = s2; }
        __syncthreads();
        s = 0.f; s2 = 0.f;
        #pragma unroll
        for (int i = 0; i < 8; i++) { s += sh[0][i]; s2 += sh[1][i]; }
        float mean = s * (1.f / 768.f);
        float var  = s2 * (1.f / 768.f) - mean * mean;
        float inv  = rsqrtf(var + 1e-5f);
        oh[row*DD + t]       = __float2half_rn((v0 - mean) * inv * g[t]       + b[t]);
        oh[row*DD + t + 256] = __float2half_rn((v1 - mean) * inv * g[t + 256] + b[t + 256]);
        oh[row*DD + t + 512] = __float2half_rn((v2 - mean) * inv * g[t + 512] + b[t + 512]);
        return;
    }
    long idx = (long)blockIdx.x * 256 + threadIdx.x;
    if (idx < QKVN) {
        int n = (int)(idx / DD), d = (int)(idx % DD);
        int h = n >> 6, cc = n & 63;
        size_t src = (size_t)h * DD * DHH + (size_t)d * DHH + cc;
        wq[idx]            = __float2half_rn(Wq[src]);
        wq[idx + QKVN]     = __float2half_rn(Wk[src]);
        wq[idx + 2 * QKVN] = __float2half_rn(Wv[src]);
        return;
    }
    idx -= QKVN;
    if (idx < WON) {
        int n = (int)(idx / DD), kk = (int)(idx % DD);
        wo[idx] = __float2half_rn(Wo[(long)kk * DD + n]);
        return;
    }
    idx -= WON;
    if (idx < W12N) {
        int n = (int)(idx / DD), kk = (int)(idx % DD);
        w1[idx] = __float2half_rn(W1[(long)kk * DFF_ + n]);
        return;
    }
    idx -= W12N;
    if (idx < W12N) {
        int n = (int)(idx / DFF_), kk = (int)(idx % DFF_);
        w2[idx] = __float2half_rn(W2[(long)kk * DD + n]);
    }
}

// ---------------- LayerNorm (fp16 in) -> fp16 ----------------
__global__ void __launch_bounds__(256) lnorm_h_kernel(
    const __half* __restrict__ x, const float* __restrict__ g, const float* __restrict__ b,
    __half* __restrict__ oh)
{
    size_t row = blockIdx.x;
    const __half* xr = x + row * DD;
    int t = threadIdx.x;
    float v0 = __half2float(xr[t]);
    float v1 = __half2float(xr[t + 256]);
    float v2 = __half2float(xr[t + 512]);
    float s  = v0 + v1 + v2;
    float s2 = v0*v0 + v1*v1 + v2*v2;
    #pragma unroll
    for (int o = 16; o; o >>= 1) {
        s  += __shfl_xor_sync(0xFFFFFFFFu, s,  o);
        s2 += __shfl_xor_sync(0xFFFFFFFFu, s2, o);
    }
    __shared__ float sh[2][8];
    int w = t >> 5, l = t & 31;
    if (l == 0) { sh[0][w] = s; sh[1][w] = s2; }
    __syncthreads();
    s = 0.f; s2 = 0.f;
    #pragma unroll
    for (int i = 0; i < 8; i++) { s += sh[0][i]; s2 += sh[1][i]; }
    float mean = s * (1.f / 768.f);
    float var  = s2 * (1.f / 768.f) - mean * mean;
    float inv  = rsqrtf(var + 1e-5f);
    oh[row*DD + t]       = __float2half_rn((v0 - mean) * inv * g[t]       + b[t]);
    oh[row*DD + t + 256] = __float2half_rn((v1 - mean) * inv * g[t + 256] + b[t + 256]);
    oh[row*DD + t + 512] = __float2half_rn((v2 - mean) * inv * g[t + 512] + b[t + 512]);
}

// ---------------- host ----------------
extern "C" void kernel_launch(void* const* d_in, const int* in_sizes, int n_in,
                              void* d_out, int out_size)
{
    (void)in_sizes; (void)n_in; (void)out_size;
    const float* x    = (const float*)d_in[0];
    const float* ln1g = (const float*)d_in[1];
    const float* ln1b = (const float*)d_in[2];
    const float* Wq   = (const float*)d_in[3];
    const float* bq   = (const float*)d_in[4];
    const float* Wk   = (const float*)d_in[5];
    const float* bk   = (const float*)d_in[6];
    const float* Wv   = (const float*)d_in[7];
    const float* bv   = (const float*)d_in[8];
    const float* Wo   = (const float*)d_in[9];
    const float* bo   = (const float*)d_in[10];
    const float* ln2g = (const float*)d_in[11];
    const float* ln2b = (const float*)d_in[12];
    const float* W1   = (const float*)d_in[13];
    const float* b1   = (const float*)d_in[14];
    const float* W2   = (const float*)d_in[15];
    const float* b2   = (const float*)d_in[16];
    float* out = (float*)d_out;

    __half *x2, *h, *q, *k, *v, *c, *ff, *wq, *wo, *w1, *w2;
    cudaGetSymbolAddress((void**)&x2,  g_x2);
    cudaGetSymbolAddress((void**)&h,   g_h);
    cudaGetSymbolAddress((void**)&q,   g_q);
    cudaGetSymbolAddress((void**)&k,   g_k);
    cudaGetSymbolAddress((void**)&v,   g_v);
    cudaGetSymbolAddress((void**)&c,   g_c);
    cudaGetSymbolAddress((void**)&ff,  g_ff);
    cudaGetSymbolAddress((void**)&wq,  g_wq);
    cudaGetSymbolAddress((void**)&wo,  g_wo);
    cudaGetSymbolAddress((void**)&w1,  g_w1);
    cudaGetSymbolAddress((void**)&w2,  g_w2);

    cudaFuncSetAttribute(tcmm, cudaFuncAttributeMaxDynamicSharedMemorySize, GSMEM);
    cudaFuncSetAttribute(flash_attn, cudaFuncAttributeMaxDynamicSharedMemorySize, FSMEM);

    // fused weight prep + ln1
    prep_ln1<<<PREP_NB + MTOK, 256>>>(
        Wq, Wk, Wv, Wo, W1, W2, wq, wo, w1, w2, x, ln1g, ln1b, h);

    // fused QKV projection (z = 0:q, 1:k, 2:v)
    {
        TcP p{};
        p.A = h; p.as_m = DD; p.a_out = 0; p.a_in = 0; p.a_zdiv = 1;
        p.B = wq; p.bs_n = DD;
        p.b_out = (long)DD * DD; p.b_in = 0; p.b_zdiv = 1;
        p.cs_m = DD; p.c_out = 0; p.c_in = 0; p.c_zdiv = 1;
        p.K = DD; p.N = DD; p.act = 0; p.qkv = 1;
        p.bias = bq; p.bias1 = bk; p.bias2 = bv;
        p.Q = q; p.K_ = k; p.V = v;
        tcmm<<<dim3(DD / 128, MTOK / 128, 3), 256, GSMEM>>>(p);
    }

    flash_attn<<<dim3(SSEQ / 128, 1, BB * HH), 256, FSMEM>>>(q, k, v, c);

    // x2 = fp16( x + ctx @ Wo + bo )
    {
        TcP s{};
        s.A = c; s.as_m = DD; s.a_out = 0; s.a_in = 0; s.a_zdiv = 1;
        s.B = wo; s.bs_n = DD; s.b_out = 0; s.b_in = 0; s.b_zdiv = 1;
        s.bias = bo; s.R = x;
        s.Cs = x2;
        s.cs_m = DD; s.c_out = 0; s.c_in = 0; s.c_zdiv = 1;
        s.K = DD; s.N = DD; s.act = 0; s.qkv = 0;
        tcmm<<<dim3(DD / 128, MTOK / 128, 1), 256, GSMEM>>>(s);
    }

    lnorm_h_kernel<<<MTOK, 256>>>(x2, ln2g, ln2b, h);

    // ff = gelu(h @ W1 + b1)
    {
        TcP s{};
        s.A = h; s.as_m = DD; s.a_out = 0; s.a_in = 0; s.a_zdiv = 1;
        s.B = w1; s.bs_n = DD; s.b_out = 0; s.b_in = 0; s.b_zdiv = 1;
        s.bias = b1;
        s.Cs = ff;
        s.cs_m = DFF_; s.c_out = 0; s.c_in = 0; s.c_zdiv = 1;
        s.K = DD; s.N = DFF_; s.act = 1; s.qkv = 0;
        tcmm<<<dim3(DFF_ / 128, MTOK / 128, 1), 256, GSMEM>>>(s);
    }

    // out = x2 + ff @ W2 + b2   (fp32 output)
    {
        TcP s{};
        s.A = ff; s.as_m = DFF_; s.a_out = 0; s.a_in = 0; s.a_zdiv = 1;
        s.B = w2; s.bs_n = DFF_; s.b_out = 0; s.b_in = 0; s.b_zdiv = 1;
        s.bias = b2; s.Rh = x2;
        s.Cf = out;
        s.cs_m = DD; s.c_out = 0; s.c_in = 0; s.c_zdiv = 1;
        s.K = DFF_; s.N = DD; s.act = 0; s.qkv = 0;
        tcmm<<<dim3(DD / 128, MTOK / 128, 1), 256, GSMEM>>>(s);
    }
}